// round 2
// baseline (speedup 1.0000x reference)
#include <cuda_runtime.h>

#define NN 100000
#define EE 3200000
#define F_IN 100
#define HID 16
#define NC 18

// Scratch (static device allocations — allowed)
__device__ __align__(128) float g_hs[NN * HID];
__device__ __align__(128) float g_acc[NN * HID];
__device__ __align__(128) float g_dinv[NN];
__device__ __align__(128) int   g_deg[NN];

// ---------------------------------------------------------------------------
// K0: zero acc + deg
__global__ void k_zero() {
    int i = blockIdx.x * blockDim.x + threadIdx.x;
    if (i < NN * HID) g_acc[i] = 0.0f;
    if (i < NN) g_deg[i] = 0;
}

// ---------------------------------------------------------------------------
// K1: degree count over edge dst (int32 indices!)
__global__ void k_deg(const int* __restrict__ dst, int E) {
    int e = blockIdx.x * blockDim.x + threadIdx.x;
    if (e < E) atomicAdd(&g_deg[dst[e]], 1);
}

// ---------------------------------------------------------------------------
// K2: h0 = relu(x@W1+b1); t = h0@Wc0; hs = dinv * t; store dinv.
// 256 threads = 16 nodes x 16 output-features per block.
__global__ void k_node0(const float* __restrict__ x,
                        const float* __restrict__ W1,
                        const float* __restrict__ b1,
                        const float* __restrict__ Wc0) {
    __shared__ float sW1[F_IN * HID];
    __shared__ float sWc0[HID * HID];
    __shared__ float sb1[HID];
    __shared__ float sx[16][F_IN];
    __shared__ float sh[16][HID];

    int tid = threadIdx.x;
    for (int i = tid; i < F_IN * HID; i += 256) sW1[i] = W1[i];
    for (int i = tid; i < HID * HID; i += 256) sWc0[i] = Wc0[i];
    if (tid < HID) sb1[tid] = b1[tid];

    int base = blockIdx.x * 16;
    // coalesced stage of 16 x-rows
    for (int i = tid; i < 16 * F_IN; i += 256) {
        sx[i / F_IN][i % F_IN] = x[(long long)(base + i / F_IN) * F_IN + (i % F_IN)];
    }
    __syncthreads();

    int ln = tid >> 4;      // local node 0..15
    int j  = tid & 15;      // output feature 0..15
    int node = base + ln;   // NN % 16 == 0, no guard needed

    float acc = sb1[j];
#pragma unroll 4
    for (int k = 0; k < F_IN; k++) acc += sx[ln][k] * sW1[k * HID + j];
    float h = fmaxf(acc, 0.0f);
    sh[ln][j] = h;
    __syncthreads();

    float t = 0.0f;
#pragma unroll
    for (int i = 0; i < HID; i++) t += sh[ln][i] * sWc0[i * HID + j];

    float dinv = rsqrtf((float)(g_deg[node] + 1));
    if (j == 0) g_dinv[node] = dinv;
    g_hs[node * HID + j] = dinv * t;
}

// ---------------------------------------------------------------------------
// K3/K5: edge scatter acc[dst] += hs[src]  (vectorized red.v4.f32)
__global__ void k_scatter(const int* __restrict__ src,
                          const int* __restrict__ dst, int E) {
    int e = blockIdx.x * blockDim.x + threadIdx.x;
    if (e >= E) return;
    int s = src[e];
    int d = dst[e];
    const float4* __restrict__ hv = (const float4*)(g_hs + s * HID);
    float4* av = (float4*)(g_acc + d * HID);
#pragma unroll
    for (int q = 0; q < 4; q++) {
        float4 v = hv[q];
        asm volatile("red.global.add.v4.f32 [%0], {%1,%2,%3,%4};"
                     :: "l"(av + q), "f"(v.x), "f"(v.y), "f"(v.z), "f"(v.w)
                     : "memory");
    }
}

// ---------------------------------------------------------------------------
// K4: h1 = relu(dinv*(acc+hs)+bc); t = h1@Wnext; hs = dinv*t; acc = 0.
__global__ void k_node1(const float* __restrict__ bc,
                        const float* __restrict__ Wnext) {
    __shared__ float sW[HID * HID];
    __shared__ float sb[HID];
    __shared__ float sh[16][HID];

    int tid = threadIdx.x;
    for (int i = tid; i < HID * HID; i += 256) sW[i] = Wnext[i];
    if (tid < HID) sb[tid] = bc[tid];
    __syncthreads();

    int ln = tid >> 4, j = tid & 15;
    int node = blockIdx.x * 16 + ln;
    int idx = node * HID + j;

    float dinv = g_dinv[node];
    float h = fmaxf(dinv * (g_acc[idx] + g_hs[idx]) + sb[j], 0.0f);
    sh[ln][j] = h;
    g_acc[idx] = 0.0f;   // re-zero for next scatter
    __syncthreads();

    float t = 0.0f;
#pragma unroll
    for (int i = 0; i < HID; i++) t += sh[ln][i] * sW[i * HID + j];
    g_hs[idx] = dinv * t;
}

// ---------------------------------------------------------------------------
// K6: h2 = relu(dinv*(acc+hs)+bc1); o = h2@W2+b2; log_softmax. Warp per node.
__global__ void k_out(const float* __restrict__ bc1,
                      const float* __restrict__ W2,
                      const float* __restrict__ b2,
                      float* __restrict__ out) {
    __shared__ float sW2[HID * NC];
    __shared__ float sb2[NC];
    __shared__ float sbc[HID];

    int tid = threadIdx.x;
    for (int i = tid; i < HID * NC; i += 256) sW2[i] = W2[i];
    if (tid < NC) sb2[tid] = b2[tid];
    if (tid < HID) sbc[tid] = bc1[tid];
    __syncthreads();

    int warp = tid >> 5, lane = tid & 31;
    int node = blockIdx.x * 8 + warp;   // NN % 8 == 0

    float dinv = g_dinv[node];
    float h = 0.0f;
    if (lane < HID) {
        int idx = node * HID + lane;
        h = fmaxf(dinv * (g_acc[idx] + g_hs[idx]) + sbc[lane], 0.0f);
    }

    float o = (lane < NC) ? sb2[lane] : -1e30f;
#pragma unroll
    for (int i = 0; i < HID; i++) {
        float hi = __shfl_sync(0xffffffff, h, i);
        if (lane < NC) o += hi * sW2[i * NC + lane];
    }

    // log-softmax over 18 classes (lanes >= NC hold -1e30 / contribute 0)
    float m = o;
#pragma unroll
    for (int off = 16; off; off >>= 1) m = fmaxf(m, __shfl_xor_sync(0xffffffff, m, off));
    float ex = (lane < NC) ? __expf(o - m) : 0.0f;
    float s = ex;
#pragma unroll
    for (int off = 16; off; off >>= 1) s += __shfl_xor_sync(0xffffffff, s, off);
    float ls = m + __logf(s);
    if (lane < NC) out[node * NC + lane] = o - ls;
}

// ---------------------------------------------------------------------------
extern "C" void kernel_launch(void* const* d_in, const int* in_sizes, int n_in,
                              void* d_out, int out_size) {
    const float* x   = (const float*)d_in[0];
    const int*   ei  = (const int*)d_in[1];     // int32! (JAX x64 disabled)
    const float* W1  = (const float*)d_in[2];
    const float* b1  = (const float*)d_in[3];
    const float* Wc0 = (const float*)d_in[4];
    const float* bc0 = (const float*)d_in[5];
    const float* Wc1 = (const float*)d_in[6];
    const float* bc1 = (const float*)d_in[7];
    const float* W2  = (const float*)d_in[8];
    const float* b2  = (const float*)d_in[9];
    float* out = (float*)d_out;

    int E = in_sizes[1] / 2;            // 3200000
    const int* src = ei;
    const int* dst = ei + E;

    int edge_blocks = (E + 255) / 256;

    k_zero<<<(NN * HID + 255) / 256, 256>>>();
    k_deg<<<edge_blocks, 256>>>(dst, E);
    k_node0<<<NN / 16, 256>>>(x, W1, b1, Wc0);
    k_scatter<<<edge_blocks, 256>>>(src, dst, E);
    k_node1<<<NN / 16, 256>>>(bc0, Wc1);
    k_scatter<<<edge_blocks, 256>>>(src, dst, E);
    k_out<<<NN / 8, 256>>>(bc1, W2, b2, out);
}

// round 4
// speedup vs baseline: 1.5462x; 1.5462x over previous
#include <cuda_runtime.h>

#define NN 100000
#define EE 3200000
#define F_IN 100
#define HID 16
#define NC 18

// Scratch (static device arrays — allowed)
__device__ __align__(128) float g_hs[NN * HID];    // dinv*[h@W] per node (conv input msg)
__device__ __align__(128) float g_hs2[NN * HID];   // double buffer for conv2
__device__ __align__(128) float g_dinv[NN];
__device__ __align__(128) int   g_deg[NN];
__device__ __align__(128) int   g_rowstart[NN + 1];
__device__ __align__(128) int   g_cursor[NN];
__device__ __align__(128) int   g_col[EE];         // CSR (by dst) column = src
__device__ __align__(128) int   g_btot[128];
__device__ __align__(128) int   g_boff[128];

#define SCAN_B 1024
#define SCAN_G 98   // 98*1024 = 100352 >= NN

// ---------------------------------------------------------------------------
// K0: zero deg, pin rowstart[NN]=E
__global__ void k_init() {
    int i = blockIdx.x * blockDim.x + threadIdx.x;
    if (i < NN) g_deg[i] = 0;
    if (i == 0) g_rowstart[NN] = EE;
}

// ---------------------------------------------------------------------------
// K1: in-degree count (int4-vectorized index loads)
__global__ void k_deg(const int* __restrict__ dst, int E) {
    int t = blockIdx.x * blockDim.x + threadIdx.x;
    int e = t * 4;
    if (e + 3 < E) {
        int4 d = *(const int4*)(dst + e);
        atomicAdd(&g_deg[d.x], 1);
        atomicAdd(&g_deg[d.y], 1);
        atomicAdd(&g_deg[d.z], 1);
        atomicAdd(&g_deg[d.w], 1);
    } else {
        for (int k = e; k < E; k++) atomicAdd(&g_deg[dst[k]], 1);
    }
}

// ---------------------------------------------------------------------------
// K2a/b/c: exclusive prefix scan of deg -> rowstart (+ cursor copy)
__global__ void k_scanA() {
    __shared__ int s[SCAN_B];
    int i = blockIdx.x * SCAN_B + threadIdx.x;
    int v = (i < NN) ? g_deg[i] : 0;
    s[threadIdx.x] = v;
    __syncthreads();
    for (int off = 1; off < SCAN_B; off <<= 1) {
        int t = (threadIdx.x >= off) ? s[threadIdx.x - off] : 0;
        __syncthreads();
        s[threadIdx.x] += t;
        __syncthreads();
    }
    if (i < NN) g_rowstart[i] = s[threadIdx.x] - v;     // exclusive within block
    if (threadIdx.x == SCAN_B - 1) g_btot[blockIdx.x] = s[threadIdx.x];
}

__global__ void k_scanB() {   // 1 block, 128 threads
    __shared__ int s[128];
    int v = (threadIdx.x < SCAN_G) ? g_btot[threadIdx.x] : 0;
    s[threadIdx.x] = v;
    __syncthreads();
    for (int off = 1; off < 128; off <<= 1) {
        int t = (threadIdx.x >= off) ? s[threadIdx.x - off] : 0;
        __syncthreads();
        s[threadIdx.x] += t;
        __syncthreads();
    }
    if (threadIdx.x < SCAN_G) g_boff[threadIdx.x] = s[threadIdx.x] - v;
}

__global__ void k_scanC() {
    int i = blockIdx.x * SCAN_B + threadIdx.x;
    if (i < NN) {
        int r = g_rowstart[i] + g_boff[blockIdx.x];
        g_rowstart[i] = r;
        g_cursor[i] = r;
    }
}

// ---------------------------------------------------------------------------
// K3: CSR fill — col[pos] = src, pos from per-dst cursor
__global__ void k_fill(const int* __restrict__ src, const int* __restrict__ dst, int E) {
    int t = blockIdx.x * blockDim.x + threadIdx.x;
    int e = t * 4;
    if (e + 3 < E) {
        int4 d = *(const int4*)(dst + e);
        int4 s = *(const int4*)(src + e);
        g_col[atomicAdd(&g_cursor[d.x], 1)] = s.x;
        g_col[atomicAdd(&g_cursor[d.y], 1)] = s.y;
        g_col[atomicAdd(&g_cursor[d.z], 1)] = s.z;
        g_col[atomicAdd(&g_cursor[d.w], 1)] = s.w;
    } else {
        for (int k = e; k < E; k++)
            g_col[atomicAdd(&g_cursor[dst[k]], 1)] = src[k];
    }
}

// ---------------------------------------------------------------------------
// K4: h0 = relu(x@W1+b1); hs = dinv * (h0@Wc0). 64 nodes/block, 256 threads:
// thread = (node ln 0..63, feature-quad jq 0..3), float4 weight loads.
__global__ void k_node0(const float* __restrict__ x,
                        const float* __restrict__ W1,
                        const float* __restrict__ b1,
                        const float* __restrict__ Wc0) {
    __shared__ __align__(16) float sx[64 * F_IN];          // 25.6 KB
    __shared__ __align__(16) float sW1[F_IN * HID];        // 6.4 KB
    __shared__ __align__(16) float sWc0[HID * HID];
    __shared__ __align__(16) float sh[64 * HID];
    __shared__ __align__(16) float sb1[HID];

    int tid = threadIdx.x;
    for (int i = tid; i < F_IN * HID; i += 256) sW1[i] = W1[i];
    for (int i = tid; i < HID * HID; i += 256) sWc0[i] = Wc0[i];
    if (tid < HID) sb1[tid] = b1[tid];

    int base = blockIdx.x * 64;
    int nrows = NN - base; if (nrows > 64) nrows = 64;
    // coalesced: sx flat == x[base*100 ..]
    for (int i = tid; i < nrows * F_IN; i += 256)
        sx[i] = x[(long long)base * F_IN + i];
    __syncthreads();

    int ln = tid >> 2, jq = tid & 3;
    int node = base + ln;
    if (node < NN) {
        float4 a = *(const float4*)&sb1[jq * 4];
        const float* xr = &sx[ln * F_IN];
#pragma unroll 4
        for (int k = 0; k < F_IN; k++) {
            float xv = xr[k];
            float4 w = *(const float4*)&sW1[k * HID + jq * 4];
            a.x += xv * w.x; a.y += xv * w.y; a.z += xv * w.z; a.w += xv * w.w;
        }
        a.x = fmaxf(a.x, 0.f); a.y = fmaxf(a.y, 0.f);
        a.z = fmaxf(a.z, 0.f); a.w = fmaxf(a.w, 0.f);
        *(float4*)&sh[ln * HID + jq * 4] = a;
    }
    __syncthreads();
    if (node < NN) {
        float4 t = {0.f, 0.f, 0.f, 0.f};
        const float* hr = &sh[ln * HID];
#pragma unroll
        for (int i = 0; i < HID; i++) {
            float hv = hr[i];
            float4 w = *(const float4*)&sWc0[i * HID + jq * 4];
            t.x += hv * w.x; t.y += hv * w.y; t.z += hv * w.z; t.w += hv * w.w;
        }
        float dinv = rsqrtf((float)(g_deg[node] + 1));
        if (jq == 0) g_dinv[node] = dinv;
        float4 o = {dinv * t.x, dinv * t.y, dinv * t.z, dinv * t.w};
        *(float4*)&g_hs[node * HID + jq * 4] = o;
    }
}

// ---------------------------------------------------------------------------
// Warp-collective CSR gather of one node's 16-feature aggregate.
// 8 edges/iter: lanes 0-7 load col indices; quad (lane&3) loads float4 slice.
// Returns per-lane feature value agg_f for f = lane (lanes 0..15 valid).
__device__ __forceinline__ float warp_gather(const float* __restrict__ hs,
                                             int node, int lane) {
    int rs = g_rowstart[node];
    int re = g_rowstart[node + 1];
    int esub = lane >> 2, q = lane & 3;
    float4 acc = {0.f, 0.f, 0.f, 0.f};
    for (int b = rs; b < re; b += 8) {
        int c = 0;
        int le = b + (lane & 7);
        if (lane < 8 && le < re) c = g_col[le];
        int s = __shfl_sync(0xffffffff, c, esub);
        if (b + esub < re) {
            float4 v = *(const float4*)&hs[s * HID + q * 4];
            acc.x += v.x; acc.y += v.y; acc.z += v.z; acc.w += v.w;
        }
    }
#pragma unroll
    for (int off = 4; off < 32; off <<= 1) {
        acc.x += __shfl_xor_sync(0xffffffff, acc.x, off);
        acc.y += __shfl_xor_sync(0xffffffff, acc.y, off);
        acc.z += __shfl_xor_sync(0xffffffff, acc.z, off);
        acc.w += __shfl_xor_sync(0xffffffff, acc.w, off);
    }
    // redistribute: lane f wants component (f&3) of quad (f>>2)'s sum
    int q2 = lane >> 2, c2 = lane & 3;
    float ax = __shfl_sync(0xffffffff, acc.x, q2);
    float ay = __shfl_sync(0xffffffff, acc.y, q2);
    float az = __shfl_sync(0xffffffff, acc.z, q2);
    float aw = __shfl_sync(0xffffffff, acc.w, q2);
    return (c2 == 0) ? ax : (c2 == 1) ? ay : (c2 == 2) ? az : aw;
}

// ---------------------------------------------------------------------------
// K5: conv1 aggregate + relu + @Wc1 + dinv, fused. Warp per node. hs -> hs2.
__global__ void k_gather_mid(const float* __restrict__ bc,
                             const float* __restrict__ Wnext) {
    __shared__ float sW[HID * HID + 32];   // padded: lanes>=16 dead-read up to [271]
    __shared__ float sb[HID];
    int tid = threadIdx.x;
    for (int i = tid; i < HID * HID; i += 256) sW[i] = Wnext[i];
    for (int i = tid + HID * HID; i < HID * HID + 32; i += 256) sW[i] = 0.f;
    if (tid < HID) sb[tid] = bc[tid];
    __syncthreads();

    int warp = tid >> 5, lane = tid & 31;
    int node = blockIdx.x * 8 + warp;     // NN % 8 == 0

    float agg = warp_gather(g_hs, node, lane);
    float dinv = g_dinv[node];
    float h = 0.f;
    if (lane < HID)
        h = fmaxf(dinv * (agg + g_hs[node * HID + lane]) + sb[lane], 0.f);

    float t = 0.f;
#pragma unroll
    for (int i = 0; i < HID; i++) {
        float hi = __shfl_sync(0xffffffff, h, i);
        t += hi * sW[i * HID + lane];     // lanes>=16 read padded zeros, discarded
    }
    if (lane < HID) g_hs2[node * HID + lane] = dinv * t;
}

// ---------------------------------------------------------------------------
// K6: conv2 aggregate + relu + @W2 + b2 + log_softmax. Warp per node.
__global__ void k_gather_out(const float* __restrict__ bc1,
                             const float* __restrict__ W2,
                             const float* __restrict__ b2,
                             float* __restrict__ out) {
    __shared__ float sW2[HID * NC];        // 288 floats — MUST use strided loop!
    __shared__ float sb2[NC];
    __shared__ float sbc[HID];
    int tid = threadIdx.x;
    for (int i = tid; i < HID * NC; i += 256) sW2[i] = W2[i];
    if (tid < NC) sb2[tid] = b2[tid];
    if (tid < HID) sbc[tid] = bc1[tid];
    __syncthreads();

    int warp = tid >> 5, lane = tid & 31;
    int node = blockIdx.x * 8 + warp;

    float agg = warp_gather(g_hs2, node, lane);
    float dinv = g_dinv[node];
    float h = 0.f;
    if (lane < HID)
        h = fmaxf(dinv * (agg + g_hs2[node * HID + lane]) + sbc[lane], 0.f);

    float o = (lane < NC) ? sb2[lane] : -1e30f;
#pragma unroll
    for (int i = 0; i < HID; i++) {
        float hi = __shfl_sync(0xffffffff, h, i);
        if (lane < NC) o += hi * sW2[i * NC + lane];
    }
    float m = o;
#pragma unroll
    for (int off = 16; off; off >>= 1) m = fmaxf(m, __shfl_xor_sync(0xffffffff, m, off));
    float ex = (lane < NC) ? __expf(o - m) : 0.f;
    float s = ex;
#pragma unroll
    for (int off = 16; off; off >>= 1) s += __shfl_xor_sync(0xffffffff, s, off);
    float ls = m + __logf(s);
    if (lane < NC) out[node * NC + lane] = o - ls;
}

// ---------------------------------------------------------------------------
extern "C" void kernel_launch(void* const* d_in, const int* in_sizes, int n_in,
                              void* d_out, int out_size) {
    const float* x   = (const float*)d_in[0];
    const int*   ei  = (const int*)d_in[1];     // int32 indices
    const float* W1  = (const float*)d_in[2];
    const float* b1  = (const float*)d_in[3];
    const float* Wc0 = (const float*)d_in[4];
    const float* bc0 = (const float*)d_in[5];
    const float* Wc1 = (const float*)d_in[6];
    const float* bc1 = (const float*)d_in[7];
    const float* W2  = (const float*)d_in[8];
    const float* b2  = (const float*)d_in[9];
    float* out = (float*)d_out;

    int E = in_sizes[1] / 2;            // 3200000
    const int* src = ei;
    const int* dst = ei + E;

    int eb4 = (E / 4 + 255) / 256;      // edge blocks, 4 edges/thread

    k_init<<<(NN + 255) / 256, 256>>>();
    k_deg<<<eb4, 256>>>(dst, E);
    k_scanA<<<SCAN_G, SCAN_B>>>();
    k_scanB<<<1, 128>>>();
    k_scanC<<<SCAN_G, SCAN_B>>>();
    k_fill<<<eb4, 256>>>(src, dst, E);
    k_node0<<<(NN + 63) / 64, 256>>>(x, W1, b1, Wc0);
    k_gather_mid<<<NN / 8, 256>>>(bc0, Wc1);
    k_gather_out<<<NN / 8, 256>>>(bc1, W2, b2, out);
}